// round 1
// baseline (speedup 1.0000x reference)
#include <cuda_runtime.h>
#include <math.h>

// Problem constants
#define Sdim 512
#define Bdim 16
#define Ddim 2048
#define Hdim 4
#define HDdim 512
#define NB 64        // Hdim * Bdim
#define Mrows 8192   // Sdim * Bdim

// GEMM tiling
#define BM 128
#define BN 128
#define BK 16
#define PAD 4

enum { MODE_PLAIN = 0, MODE_QKV = 1, MODE_SCORES = 2, MODE_PV = 3 };

// Scratch (device globals; no allocation allowed)
__device__ float g_Qh[(size_t)NB * Sdim * HDdim];
__device__ float g_Kh[(size_t)NB * Sdim * HDdim];
__device__ float g_Vh[(size_t)NB * Sdim * HDdim];
__device__ float g_scores[(size_t)NB * Sdim * Sdim];
__device__ float g_Cperm[(size_t)Mrows * Ddim];
__device__ float g_attn_fb[(size_t)NB * Sdim * Sdim];

// Generic SGEMM: C = alpha * A * op(B)
// BLOADNN==0: NT  (C[m,n] = sum_k A[m,k]*B[n,k]; B row-major [N,K], row stride ldb)
// BLOADNN==1: NN  (C[m,n] = sum_k A[m,k]*B[k,n]; B row-major [K,N], row stride ldb)
// All dims assumed multiples of tile sizes (true for this problem).
template <int BLOADNN>
__global__ __launch_bounds__(256, 2)
void sgemm_kernel(const float* __restrict__ A, int lda,
                  const float* __restrict__ Bp, int ldb,
                  float* __restrict__ C, int ldc,
                  int K, float alpha, int mode)
{
    __shared__ float As[BK][BM + PAD];
    __shared__ float Bs[BK][BN + PAD];

    const int t  = threadIdx.x;
    const int tx = t & 15;        // 0..15
    const int ty = t >> 4;        // 0..15
    const int m0 = blockIdx.y * BM;
    const int n0 = blockIdx.x * BN;

    long aOff = 0, bOff = 0, cBase = 0;
    if (mode == MODE_SCORES) {
        long z = blockIdx.z;
        aOff  = z * (long)Sdim * HDdim;
        bOff  = z * (long)Sdim * HDdim;
        cBase = z * (long)Sdim * Sdim;
    } else if (mode == MODE_PV) {
        int z = blockIdx.z;
        int h = z >> 4;           // z / Bdim
        int b = z & 15;           // z % Bdim
        aOff  = (long)b * Sdim * Hdim * HDdim + (long)h * HDdim;     // attn[b, s, h, t]
        bOff  = (long)z * Sdim * HDdim;                               // Vh[n, t, d]
        cBase = ((long)b * Hdim + h) * (long)Sdim * HDdim;            // Cperm[b, h, s, d]
    }
    const float* Ab = A  + aOff;
    const float* Bb = Bp + bOff;

    float acc[8][8];
#pragma unroll
    for (int i = 0; i < 8; i++)
#pragma unroll
        for (int j = 0; j < 8; j++) acc[i][j] = 0.f;

    for (int kt = 0; kt < K; kt += BK) {
        // Load A tile: 128 rows x 16 cols = 512 float4, 2 per thread; store transposed
#pragma unroll
        for (int i = 0; i < 2; i++) {
            int idx = t + i * 256;
            int row = idx >> 2;          // 0..127
            int c4  = idx & 3;           // 0..3 (float4 within row)
            float4 v = *(const float4*)(Ab + (long)(m0 + row) * lda + kt + c4 * 4);
            As[c4 * 4 + 0][row] = v.x;
            As[c4 * 4 + 1][row] = v.y;
            As[c4 * 4 + 2][row] = v.z;
            As[c4 * 4 + 3][row] = v.w;
        }
        if (BLOADNN == 0) {
            // NT: B tile rows are n-indices, cols k
#pragma unroll
            for (int i = 0; i < 2; i++) {
                int idx = t + i * 256;
                int row = idx >> 2;
                int c4  = idx & 3;
                float4 v = *(const float4*)(Bb + (long)(n0 + row) * ldb + kt + c4 * 4);
                Bs[c4 * 4 + 0][row] = v.x;
                Bs[c4 * 4 + 1][row] = v.y;
                Bs[c4 * 4 + 2][row] = v.z;
                Bs[c4 * 4 + 3][row] = v.w;
            }
        } else {
            // NN: B tile rows are k-indices (16), cols n (128)
#pragma unroll
            for (int i = 0; i < 2; i++) {
                int idx = t + i * 256;
                int row = idx >> 5;          // 0..15
                int c4  = idx & 31;          // 0..31
                float4 v = *(const float4*)(Bb + (long)(kt + row) * ldb + n0 + c4 * 4);
                *(float4*)(&Bs[row][c4 * 4]) = v;
            }
        }
        __syncthreads();

#pragma unroll
        for (int k = 0; k < BK; k++) {
            float a[8], bv[8];
            *(float4*)(&a[0])  = *(const float4*)(&As[k][ty * 4]);
            *(float4*)(&a[4])  = *(const float4*)(&As[k][64 + ty * 4]);
            *(float4*)(&bv[0]) = *(const float4*)(&Bs[k][tx * 4]);
            *(float4*)(&bv[4]) = *(const float4*)(&Bs[k][64 + tx * 4]);
#pragma unroll
            for (int i = 0; i < 8; i++)
#pragma unroll
                for (int j = 0; j < 8; j++)
                    acc[i][j] = fmaf(a[i], bv[j], acc[i][j]);
        }
        __syncthreads();
    }

    // Epilogue: rows r = m0 + ih*64 + ty*4 + i ; cols c = n0 + jh*64 + tx*4 + j
#pragma unroll
    for (int ih = 0; ih < 2; ih++) {
#pragma unroll
        for (int i = 0; i < 4; i++) {
            int r = m0 + ih * 64 + ty * 4 + i;
#pragma unroll
            for (int jh = 0; jh < 2; jh++) {
                int c = n0 + jh * 64 + tx * 4;   // aligned to 4
                float4 vec;
                vec.x = acc[ih * 4 + i][jh * 4 + 0] * alpha;
                vec.y = acc[ih * 4 + i][jh * 4 + 1] * alpha;
                vec.z = acc[ih * 4 + i][jh * 4 + 2] * alpha;
                vec.w = acc[ih * 4 + i][jh * 4 + 3] * alpha;
                long oi;
                if (mode == MODE_QKV) {
                    // r = s*Bdim + b ; c = h*HDdim + d
                    int s  = r >> 4;
                    int bb = r & 15;
                    int h  = c >> 9;
                    int d  = c & 511;
                    oi = (((long)h * Bdim + bb) * Sdim + s) * HDdim + d;
                } else {
                    oi = cBase + (long)r * ldc + c;
                }
                *(float4*)(&C[oi]) = vec;
            }
        }
    }
}

// Softmax: one warp per row of scores[n][s][0..511]; writes attn[b][s][h][t]
__global__ void softmax_kernel(const float* __restrict__ scores, float* __restrict__ attn)
{
    int gwarp = (blockIdx.x * blockDim.x + threadIdx.x) >> 5;
    int lane  = threadIdx.x & 31;
    if (gwarp >= NB * Sdim) return;
    int n = gwarp >> 9;       // / Sdim
    int s = gwarp & 511;
    int h = n >> 4;           // n / Bdim
    int b = n & 15;           // n % Bdim

    const float* row = scores + ((long)n * Sdim + s) * Sdim;
    float vals[16];
    float mx = -1e30f;
#pragma unroll
    for (int i = 0; i < 16; i++) {
        vals[i] = row[lane + i * 32];
        mx = fmaxf(mx, vals[i]);
    }
#pragma unroll
    for (int o = 16; o > 0; o >>= 1) mx = fmaxf(mx, __shfl_xor_sync(0xffffffffu, mx, o));
    float sum = 0.f;
#pragma unroll
    for (int i = 0; i < 16; i++) {
        vals[i] = expf(vals[i] - mx);
        sum += vals[i];
    }
#pragma unroll
    for (int o = 16; o > 0; o >>= 1) sum += __shfl_xor_sync(0xffffffffu, sum, o);
    float inv = 1.f / sum;

    float* orow = attn + (((long)b * Sdim + s) * Hdim + h) * HDdim;
#pragma unroll
    for (int i = 0; i < 16; i++) orow[lane + i * 32] = vals[i] * inv;
}

extern "C" void kernel_launch(void* const* d_in, const int* in_sizes, int n_in,
                              void* d_out, int out_size)
{
    const float* q  = (const float*)d_in[0];
    const float* k  = (const float*)d_in[1];
    const float* v  = (const float*)d_in[2];
    const float* Wq = (const float*)d_in[3];
    const float* Wk = (const float*)d_in[4];
    const float* Wv = (const float*)d_in[5];
    const float* Wo = (const float*)d_in[6];
    float* out = (float*)d_out;

    float *Qh, *Kh, *Vh, *Sc, *Cp, *At;
    cudaGetSymbolAddress((void**)&Qh, g_Qh);
    cudaGetSymbolAddress((void**)&Kh, g_Kh);
    cudaGetSymbolAddress((void**)&Vh, g_Vh);
    cudaGetSymbolAddress((void**)&Sc, g_scores);
    cudaGetSymbolAddress((void**)&Cp, g_Cperm);
    cudaGetSymbolAddress((void**)&At, g_attn_fb);

    const long MAIN_OUT = (long)Mrows * Ddim;             // 16,777,216
    float* attn_out = ((long)out_size >= 2 * MAIN_OUT) ? (out + MAIN_OUT) : At;

    dim3 blk(256);
    dim3 gProj(Ddim / BN, Mrows / BM);                    // 16 x 64
    dim3 gAttn(Sdim / BN, Sdim / BM, NB);                 // 4 x 4 x 64

    // 1-3. Q/K/V projections with head-split epilogue
    sgemm_kernel<0><<<gProj, blk>>>(q, Ddim, Wq, Ddim, Qh, 0, Ddim, 1.0f, MODE_QKV);
    sgemm_kernel<0><<<gProj, blk>>>(k, Ddim, Wk, Ddim, Kh, 0, Ddim, 1.0f, MODE_QKV);
    sgemm_kernel<0><<<gProj, blk>>>(v, Ddim, Wv, Ddim, Vh, 0, Ddim, 1.0f, MODE_QKV);

    // 4. scores = Q @ K^T / sqrt(hd)  (batched over 64 heads)
    const float scale = 0.044194173824159223f;            // 1/sqrt(512)
    sgemm_kernel<0><<<gAttn, blk>>>(Qh, HDdim, Kh, HDdim, Sc, Sdim, HDdim, scale, MODE_SCORES);

    // 5. softmax rows -> attn written in (B,S,H,t) permuted layout (= attn_score output)
    {
        int totalWarps = NB * Sdim;                       // 32768
        int threads = 256;
        int blocks = (totalWarps * 32 + threads - 1) / threads;
        softmax_kernel<<<blocks, threads>>>(Sc, attn_out);
    }

    // 6. context = P @ V (batched, NN), written in (B,H,S,d) linear order
    sgemm_kernel<1><<<gAttn, blk>>>(attn_out, Hdim * HDdim, Vh, HDdim, Cp, HDdim, Sdim, 1.0f, MODE_PV);

    // 7. output = Cperm(viewed [8192,2048]) @ Wo^T
    sgemm_kernel<0><<<gProj, blk>>>(Cp, Ddim, Wo, Ddim, out, Ddim, Ddim, 1.0f, MODE_PLAIN);
}

// round 3
// speedup vs baseline: 2.0465x; 2.0465x over previous
#include <cuda_runtime.h>
#include <cuda_bf16.h>
#include <stdint.h>
#include <math.h>

// Problem constants
#define Sdim 512
#define Bdim 16
#define Ddim 2048
#define Hdim 4
#define HDdim 512
#define NB 64                      // Hdim*Bdim heads total
#define Mrows 8192                 // Sdim*Bdim
#define HEAD_ELEMS (Sdim * HDdim)  // 262144

// ---------------- scratch (device globals; no allocation allowed) ----------
__device__ __nv_bfloat16 g_Ahi[(size_t)Mrows * Ddim];
__device__ __nv_bfloat16 g_Alo[(size_t)Mrows * Ddim];
__device__ __nv_bfloat16 g_Whi[(size_t)Ddim * Ddim];
__device__ __nv_bfloat16 g_Wlo[(size_t)Ddim * Ddim];
__device__ __nv_bfloat16 g_Qhi[(size_t)NB * HEAD_ELEMS];
__device__ __nv_bfloat16 g_Qlo[(size_t)NB * HEAD_ELEMS];
__device__ __nv_bfloat16 g_Khi[(size_t)NB * HEAD_ELEMS];
__device__ __nv_bfloat16 g_Klo[(size_t)NB * HEAD_ELEMS];
__device__ float         g_Vh  [(size_t)NB * HEAD_ELEMS];
__device__ __nv_bfloat16 g_Vthi[(size_t)NB * HEAD_ELEMS];
__device__ __nv_bfloat16 g_Vtlo[(size_t)NB * HEAD_ELEMS];
__device__ float         g_scores [(size_t)NB * HEAD_ELEMS];
__device__ float         g_attn_fb[(size_t)NB * HEAD_ELEMS];
__device__ __nv_bfloat16 g_Phi[(size_t)NB * HEAD_ELEMS];
__device__ __nv_bfloat16 g_Plo[(size_t)NB * HEAD_ELEMS];
__device__ __nv_bfloat16 g_Chi[(size_t)Mrows * Ddim];
__device__ __nv_bfloat16 g_Clo[(size_t)Mrows * Ddim];

// ---------------- PTX helpers (base ISA only: sm_80+ features) --------------
__device__ __forceinline__ uint32_t smem_u32(const void* p) {
    uint32_t a;
    asm("{ .reg .u64 t; cvta.to.shared.u64 t, %1; cvt.u32.u64 %0, t; }" : "=r"(a) : "l"(p));
    return a;
}
#define CP_ASYNC16(dst, src) \
    asm volatile("cp.async.cg.shared.global [%0], [%1], 16;" :: "r"(dst), "l"(src))
#define CP_COMMIT  asm volatile("cp.async.commit_group;" ::: "memory")
#define CP_WAIT0   asm volatile("cp.async.wait_group 0;" ::: "memory")
#define CP_WAIT1   asm volatile("cp.async.wait_group 1;" ::: "memory")

__device__ __forceinline__ void ldsm4(uint32_t* r, uint32_t addr) {
    asm volatile("ldmatrix.sync.aligned.m8n8.x4.shared.b16 {%0,%1,%2,%3}, [%4];"
                 : "=r"(r[0]), "=r"(r[1]), "=r"(r[2]), "=r"(r[3]) : "r"(addr));
}
__device__ __forceinline__ void mma_bf16(float* c, const uint32_t* a, const uint32_t* b) {
    asm volatile(
        "mma.sync.aligned.m16n8k16.row.col.f32.bf16.bf16.f32 "
        "{%0,%1,%2,%3}, {%4,%5,%6,%7}, {%8,%9}, {%0,%1,%2,%3};"
        : "+f"(c[0]), "+f"(c[1]), "+f"(c[2]), "+f"(c[3])
        : "r"(a[0]), "r"(a[1]), "r"(a[2]), "r"(a[3]), "r"(b[0]), "r"(b[1]));
}

__device__ __forceinline__ void wr_hilo2(__nv_bfloat16* H, __nv_bfloat16* L,
                                         size_t off, float a, float b) {
    __nv_bfloat16 ha = __float2bfloat16(a), hb = __float2bfloat16(b);
    __nv_bfloat162 hv; hv.x = ha; hv.y = hb;
    __nv_bfloat162 lv;
    lv.x = __float2bfloat16(a - __bfloat162float(ha));
    lv.y = __float2bfloat16(b - __bfloat162float(hb));
    *(__nv_bfloat162*)(H + off) = hv;
    *(__nv_bfloat162*)(L + off) = lv;
}

// ---------------- mma.sync NT GEMM ------------------------------------------
// C[M,N] = alpha * A[M,K] * B[N,K]^T with A,B as bf16 hi/lo pairs (3-pass).
// Block 128x128, BK=32, 256 threads; warp tile 32x64 (warps: 4 in m, 2 in n).
#define GBM 128
#define GBN 128
#define GBK 32
#define ROW_B 80                 // smem bytes per tile row (32 bf16 + 8 pad)
#define TILE_B (128 * ROW_B)     // 10240
#define STAGE_B (4 * TILE_B)     // Ahi,Alo,Bhi,Blo = 40960
#define GEMM_SMEM (2 * STAGE_B)  // 81920

enum { EP_F32 = 0, EP_BF16 = 1, EP_QK = 2, EP_V = 3 };

// r = s*16 + b (or t*16 + b), c = h*512 + d  ->  ((b*4+h)*512 + s)*512 + d
__device__ __forceinline__ size_t headperm_idx(int r, int c) {
    int s = r >> 4, bb = r & 15, h = c >> 9, d = c & 511;
    return (((size_t)(bb * Hdim + h) * Sdim + s) * HDdim + d);
}

struct GemmArgs {
    const __nv_bfloat16 *Ahi, *Alo, *Bhi, *Blo;
    int lda, ldb, ldc, K;
    size_t bsA, bsB, bsC;
    float* Cf;
    __nv_bfloat16 *Chi, *Clo;
    float alpha;
    int mode;
};

__global__ __launch_bounds__(256, 1)
void mma_gemm(GemmArgs g)
{
    extern __shared__ char smraw[];
    const uint32_t sb = smem_u32(smraw);
    const int tid = threadIdx.x;
    const int lane = tid & 31;
    const int wid = tid >> 5;
    const int wm = wid & 3;       // warp m index (0..3)
    const int wn = wid >> 2;      // warp n index (0..1)
    const int m0 = blockIdx.y * GBM;
    const int n0 = blockIdx.x * GBN;
    const size_t z = blockIdx.z;

    const __nv_bfloat16* Ah = g.Ahi + z * g.bsA;
    const __nv_bfloat16* Al = g.Alo + z * g.bsA;
    const __nv_bfloat16* Bh = g.Bhi + z * g.bsB;
    const __nv_bfloat16* Bl = g.Blo + z * g.bsB;

    float acc[2][8][4];
#pragma unroll
    for (int i = 0; i < 2; i++)
#pragma unroll
        for (int j = 0; j < 8; j++)
#pragma unroll
            for (int x = 0; x < 4; x++) acc[i][j][x] = 0.f;

    // ldmatrix address precompute (per-thread, stage-relative)
    const uint32_t a_mrow = (uint32_t)(wm * 32) + (lane & 15);
    const uint32_t a_kadd = (uint32_t)(((lane >> 4) & 1) << 3);   // +8 bf16
    const uint32_t b_nrow = (uint32_t)(wn * 64) + (lane & 7) + (((lane >> 4) & 1) << 3);
    const uint32_t b_kadd = (uint32_t)(((lane >> 3) & 1) << 3);

    const int NCH = g.K >> 5;

    // -------- cp.async stage fill --------
    auto issue = [&](int ch, int stg) {
        const int kOff = ch * GBK;
        const uint32_t stb = sb + (uint32_t)stg * STAGE_B;
#pragma unroll
        for (int t4 = 0; t4 < 4; t4++) {
            const __nv_bfloat16* base = (t4 == 0) ? Ah : (t4 == 1) ? Al : (t4 == 2) ? Bh : Bl;
            const int ld = (t4 < 2) ? g.lda : g.ldb;
            const int r0 = (t4 < 2) ? m0 : n0;
#pragma unroll
            for (int j = 0; j < 2; j++) {
                int id = tid + j * 256;          // 0..511
                int row = id >> 2;               // 0..127
                int cc = id & 3;                 // 16B chunk
                uint32_t dst = stb + (uint32_t)t4 * TILE_B + (uint32_t)row * ROW_B + (uint32_t)cc * 16;
                const void* src = base + (size_t)(r0 + row) * ld + kOff + cc * 8;
                CP_ASYNC16(dst, src);
            }
        }
        CP_COMMIT;
    };

    auto compute = [&](int stg) {
        const uint32_t stb = sb + (uint32_t)stg * STAGE_B;
        const uint32_t ahB = stb;
        const uint32_t alB = stb + TILE_B;
        const uint32_t bhB = stb + 2 * TILE_B;
        const uint32_t blB = stb + 3 * TILE_B;
#pragma unroll
        for (int ks = 0; ks < 2; ks++) {
            uint32_t afh[2][4], afl[2][4];
#pragma unroll
            for (int i = 0; i < 2; i++) {
                uint32_t off = (a_mrow + (uint32_t)(i * 16)) * ROW_B +
                               ((uint32_t)(ks * 16) + a_kadd) * 2;
                ldsm4(afh[i], ahB + off);
                ldsm4(afl[i], alB + off);
            }
#pragma unroll
            for (int gnp = 0; gnp < 4; gnp++) {   // groups of 2 n-tiles
                uint32_t bfh[4], bfl[4];
                uint32_t off = (b_nrow + (uint32_t)(gnp * 16)) * ROW_B +
                               ((uint32_t)(ks * 16) + b_kadd) * 2;
                ldsm4(bfh, bhB + off);
                ldsm4(bfl, blB + off);
#pragma unroll
                for (int i = 0; i < 2; i++) {
#pragma unroll
                    for (int jj = 0; jj < 2; jj++) {
                        float* c = acc[i][gnp * 2 + jj];
                        mma_bf16(c, afh[i], bfh + jj * 2);
                        mma_bf16(c, afh[i], bfl + jj * 2);
                        mma_bf16(c, afl[i], bfh + jj * 2);
                    }
                }
            }
        }
    };

    issue(0, 0);
    for (int ch = 0; ch < NCH; ch++) {
        const int p = ch & 1;
        if (ch + 1 < NCH) { issue(ch + 1, p ^ 1); CP_WAIT1; }
        else              { CP_WAIT0; }
        __syncthreads();
        compute(p);
        __syncthreads();
    }

    // -------- epilogue --------
    const int quad = lane >> 2, tq = lane & 3;
    const float alpha = g.alpha;
#pragma unroll
    for (int i = 0; i < 2; i++) {
#pragma unroll
        for (int jj = 0; jj < 8; jj++) {
            const int r  = m0 + wm * 32 + i * 16 + quad;
            const int c  = n0 + wn * 64 + jj * 8 + tq * 2;
            const float v0 = acc[i][jj][0] * alpha;
            const float v1 = acc[i][jj][1] * alpha;
            const float v2 = acc[i][jj][2] * alpha;
            const float v3 = acc[i][jj][3] * alpha;
            if (g.mode == EP_F32) {
                float2* p0 = (float2*)(g.Cf + z * g.bsC + (size_t)r * g.ldc + c);
                float2* p1 = (float2*)(g.Cf + z * g.bsC + (size_t)(r + 8) * g.ldc + c);
                float2 a0; a0.x = v0; a0.y = v1; *p0 = a0;
                float2 a1; a1.x = v2; a1.y = v3; *p1 = a1;
            } else if (g.mode == EP_BF16) {
                wr_hilo2(g.Chi, g.Clo, z * g.bsC + (size_t)r * g.ldc + c, v0, v1);
                wr_hilo2(g.Chi, g.Clo, z * g.bsC + (size_t)(r + 8) * g.ldc + c, v2, v3);
            } else if (g.mode == EP_QK) {
                wr_hilo2(g.Chi, g.Clo, headperm_idx(r, c), v0, v1);
                wr_hilo2(g.Chi, g.Clo, headperm_idx(r + 8, c), v2, v3);
            } else { // EP_V : fp32 head-permuted
                size_t o0 = headperm_idx(r, c), o1 = headperm_idx(r + 8, c);
                float2 a0; a0.x = v0; a0.y = v1; *(float2*)(g.Cf + o0) = a0;
                float2 a1; a1.x = v2; a1.y = v3; *(float2*)(g.Cf + o1) = a1;
            }
        }
    }
}

// ---------------- fp32 -> bf16 hi/lo split -----------------------------------
__global__ void cvt_hilo(const float* __restrict__ x, __nv_bfloat16* __restrict__ hi,
                         __nv_bfloat16* __restrict__ lo, int n4)
{
    int i = blockIdx.x * blockDim.x + threadIdx.x;
    if (i >= n4) return;
    float4 v = ((const float4*)x)[i];
    float f[4] = {v.x, v.y, v.z, v.w};
    __nv_bfloat162 h2[2], l2[2];
#pragma unroll
    for (int j = 0; j < 2; j++) {
        __nv_bfloat16 ha = __float2bfloat16(f[j * 2 + 0]);
        __nv_bfloat16 hb = __float2bfloat16(f[j * 2 + 1]);
        h2[j].x = ha; h2[j].y = hb;
        l2[j].x = __float2bfloat16(f[j * 2 + 0] - __bfloat162float(ha));
        l2[j].y = __float2bfloat16(f[j * 2 + 1] - __bfloat162float(hb));
    }
    ((__nv_bfloat162*)hi)[i * 2 + 0] = h2[0];
    ((__nv_bfloat162*)hi)[i * 2 + 1] = h2[1];
    ((__nv_bfloat162*)lo)[i * 2 + 0] = l2[0];
    ((__nv_bfloat162*)lo)[i * 2 + 1] = l2[1];
}

// ---------------- V transpose + split: Vh[gb][t][d] -> Vt[gb][d][t] ---------
__global__ void vtrans_kernel(const float* __restrict__ Vh,
                              __nv_bfloat16* __restrict__ Vthi,
                              __nv_bfloat16* __restrict__ Vtlo)
{
    __shared__ float tile[32][33];
    const int gb = blockIdx.z;
    const int t0 = blockIdx.x * 32;
    const int d0 = blockIdx.y * 32;
    const int tx = threadIdx.x, ty = threadIdx.y;   // 32 x 8
    const float* src = Vh + (size_t)gb * HEAD_ELEMS;
#pragma unroll
    for (int i = 0; i < 32; i += 8)
        tile[ty + i][tx] = src[(size_t)(t0 + ty + i) * HDdim + d0 + tx];
    __syncthreads();
    __nv_bfloat16* dh = Vthi + (size_t)gb * HEAD_ELEMS;
    __nv_bfloat16* dl = Vtlo + (size_t)gb * HEAD_ELEMS;
#pragma unroll
    for (int i = 0; i < 32; i += 8) {
        float v = tile[tx][ty + i];
        __nv_bfloat16 h = __float2bfloat16(v);
        size_t o = (size_t)(d0 + ty + i) * Sdim + t0 + tx;
        dh[o] = h;
        dl[o] = __float2bfloat16(v - __bfloat162float(h));
    }
}

// ---------------- softmax: scores[gb][s][t] -> attn fp32 + P hi/lo ----------
__global__ void softmax_kernel(const float* __restrict__ scores,
                               float* __restrict__ attn,
                               __nv_bfloat16* __restrict__ Phi,
                               __nv_bfloat16* __restrict__ Plo)
{
    int gwarp = (blockIdx.x * blockDim.x + threadIdx.x) >> 5;
    int lane  = threadIdx.x & 31;
    if (gwarp >= NB * Sdim) return;
    int gb = gwarp >> 9;         // head slot (b*4+h)
    int s  = gwarp & 511;
    int b  = gb >> 2;
    int h  = gb & 3;

    const float* row = scores + ((size_t)gb * Sdim + s) * Sdim;
    float vals[16];
    float mx = -1e30f;
#pragma unroll
    for (int i = 0; i < 16; i++) {
        vals[i] = row[lane + i * 32];
        mx = fmaxf(mx, vals[i]);
    }
#pragma unroll
    for (int o = 16; o > 0; o >>= 1) mx = fmaxf(mx, __shfl_xor_sync(0xffffffffu, mx, o));
    float sum = 0.f;
#pragma unroll
    for (int i = 0; i < 16; i++) {
        vals[i] = expf(vals[i] - mx);
        sum += vals[i];
    }
#pragma unroll
    for (int o = 16; o > 0; o >>= 1) sum += __shfl_xor_sync(0xffffffffu, sum, o);
    float inv = 1.f / sum;

    float* arow = attn + (((size_t)b * Sdim + s) * Hdim + h) * HDdim;   // [b][s][h][t]
    __nv_bfloat16* ph = Phi + ((size_t)gb * Sdim + s) * Sdim;
    __nv_bfloat16* pl = Plo + ((size_t)gb * Sdim + s) * Sdim;
#pragma unroll
    for (int i = 0; i < 16; i++) {
        float p = vals[i] * inv;
        arow[lane + i * 32] = p;
        __nv_bfloat16 hh = __float2bfloat16(p);
        ph[lane + i * 32] = hh;
        pl[lane + i * 32] = __float2bfloat16(p - __bfloat162float(hh));
    }
}

// ---------------- launch -----------------------------------------------------
extern "C" void kernel_launch(void* const* d_in, const int* in_sizes, int n_in,
                              void* d_out, int out_size)
{
    const float* q  = (const float*)d_in[0];
    const float* k  = (const float*)d_in[1];
    const float* v  = (const float*)d_in[2];
    const float* Wq = (const float*)d_in[3];
    const float* Wk = (const float*)d_in[4];
    const float* Wv = (const float*)d_in[5];
    const float* Wo = (const float*)d_in[6];
    float* out = (float*)d_out;

    __nv_bfloat16 *Ahi, *Alo, *Whi, *Wlo, *Qhi, *Qlo, *Khi, *Klo, *Vthi, *Vtlo, *Phi, *Plo, *Chi, *Clo;
    float *Vh, *Sc, *At;
    cudaGetSymbolAddress((void**)&Ahi, g_Ahi);   cudaGetSymbolAddress((void**)&Alo, g_Alo);
    cudaGetSymbolAddress((void**)&Whi, g_Whi);   cudaGetSymbolAddress((void**)&Wlo, g_Wlo);
    cudaGetSymbolAddress((void**)&Qhi, g_Qhi);   cudaGetSymbolAddress((void**)&Qlo, g_Qlo);
    cudaGetSymbolAddress((void**)&Khi, g_Khi);   cudaGetSymbolAddress((void**)&Klo, g_Klo);
    cudaGetSymbolAddress((void**)&Vh,  g_Vh);
    cudaGetSymbolAddress((void**)&Vthi, g_Vthi); cudaGetSymbolAddress((void**)&Vtlo, g_Vtlo);
    cudaGetSymbolAddress((void**)&Sc,  g_scores);
    cudaGetSymbolAddress((void**)&At,  g_attn_fb);
    cudaGetSymbolAddress((void**)&Phi, g_Phi);   cudaGetSymbolAddress((void**)&Plo, g_Plo);
    cudaGetSymbolAddress((void**)&Chi, g_Chi);   cudaGetSymbolAddress((void**)&Clo, g_Clo);

    const long MAIN_OUT = (long)Mrows * Ddim;
    float* attn_out = ((long)out_size >= 2 * MAIN_OUT) ? (out + MAIN_OUT) : At;

    cudaFuncSetAttribute(mma_gemm, cudaFuncAttributeMaxDynamicSharedMemorySize, GEMM_SMEM);

    const int nAct4 = (Mrows * Ddim) / 4;
    const int nW4   = (Ddim * Ddim) / 4;
    dim3 cblk(256);
    dim3 gActCvt(nAct4 / 256), gWCvt(nW4 / 256);
    dim3 blk(256);
    dim3 gProj(Ddim / GBN, Mrows / GBM, 1);      // 16 x 64
    dim3 gAttn(HDdim / GBN, Sdim / GBM, NB);     // 4 x 4 x 64

    GemmArgs ga;
    ga.lda = Ddim; ga.ldb = Ddim; ga.ldc = Ddim; ga.K = Ddim;
    ga.bsA = 0; ga.bsB = 0; ga.bsC = 0;
    ga.alpha = 1.0f;

    // ---- Q projection ----
    cvt_hilo<<<gActCvt, cblk>>>(q, Ahi, Alo, nAct4);
    cvt_hilo<<<gWCvt, cblk>>>(Wq, Whi, Wlo, nW4);
    ga.Ahi = Ahi; ga.Alo = Alo; ga.Bhi = Whi; ga.Blo = Wlo;
    ga.Cf = nullptr; ga.Chi = Qhi; ga.Clo = Qlo; ga.mode = EP_QK;
    mma_gemm<<<gProj, blk, GEMM_SMEM>>>(ga);
    // ---- K projection ----
    cvt_hilo<<<gActCvt, cblk>>>(k, Ahi, Alo, nAct4);
    cvt_hilo<<<gWCvt, cblk>>>(Wk, Whi, Wlo, nW4);
    ga.Chi = Khi; ga.Clo = Klo; ga.mode = EP_QK;
    mma_gemm<<<gProj, blk, GEMM_SMEM>>>(ga);
    // ---- V projection (fp32 head-permuted) ----
    cvt_hilo<<<gActCvt, cblk>>>(v, Ahi, Alo, nAct4);
    cvt_hilo<<<gWCvt, cblk>>>(Wv, Whi, Wlo, nW4);
    ga.Cf = Vh; ga.Chi = nullptr; ga.Clo = nullptr; ga.mode = EP_V;
    mma_gemm<<<gProj, blk, GEMM_SMEM>>>(ga);
    // ---- V transpose + bf16 split ----
    {
        dim3 tb(32, 8);
        dim3 tg(Sdim / 32, HDdim / 32, NB);
        vtrans_kernel<<<tg, tb>>>(Vh, Vthi, Vtlo);
    }
    // ---- scores = Q K^T / sqrt(hd) ----
    {
        GemmArgs gs;
        gs.Ahi = Qhi; gs.Alo = Qlo; gs.Bhi = Khi; gs.Blo = Klo;
        gs.lda = HDdim; gs.ldb = HDdim; gs.ldc = Sdim; gs.K = HDdim;
        gs.bsA = HEAD_ELEMS; gs.bsB = HEAD_ELEMS; gs.bsC = HEAD_ELEMS;
        gs.Cf = Sc; gs.Chi = nullptr; gs.Clo = nullptr;
        gs.alpha = 0.044194173824159223f;   // 1/sqrt(512)
        gs.mode = EP_F32;
        mma_gemm<<<gAttn, blk, GEMM_SMEM>>>(gs);
    }
    // ---- softmax -> attn fp32 output + P hi/lo ----
    {
        int totalWarps = NB * Sdim;
        int blocks = (totalWarps * 32) / 256;
        softmax_kernel<<<blocks, 256>>>(Sc, attn_out, Phi, Plo);
    }
    // ---- context = P V  -> Chi/Clo in (b,h,s,d) linear order ----
    {
        GemmArgs gp;
        gp.Ahi = Phi; gp.Alo = Plo; gp.Bhi = Vthi; gp.Blo = Vtlo;
        gp.lda = Sdim; gp.ldb = Sdim; gp.ldc = HDdim; gp.K = Sdim;
        gp.bsA = HEAD_ELEMS; gp.bsB = HEAD_ELEMS; gp.bsC = HEAD_ELEMS;
        gp.Cf = nullptr; gp.Chi = Chi; gp.Clo = Clo;
        gp.alpha = 1.0f; gp.mode = EP_BF16;
        mma_gemm<<<gAttn, blk, GEMM_SMEM>>>(gp);
    }
    // ---- output = C @ Wo^T ----
    cvt_hilo<<<gWCvt, cblk>>>(Wo, Whi, Wlo, nW4);
    {
        GemmArgs go;
        go.Ahi = Chi; go.Alo = Clo; go.Bhi = Whi; go.Blo = Wlo;
        go.lda = Ddim; go.ldb = Ddim; go.ldc = Ddim; go.K = Ddim;
        go.bsA = 0; go.bsB = 0; go.bsC = 0;
        go.Cf = out; go.Chi = nullptr; go.Clo = nullptr;
        go.alpha = 1.0f; go.mode = EP_F32;
        mma_gemm<<<gProj, blk, GEMM_SMEM>>>(go);
    }
}

// round 4
// speedup vs baseline: 2.1455x; 1.0484x over previous
#include <cuda_runtime.h>
#include <cuda_bf16.h>
#include <stdint.h>
#include <math.h>

// Problem constants
#define Sdim 512
#define Bdim 16
#define Ddim 2048
#define Hdim 4
#define HDdim 512
#define NB 64                      // Hdim*Bdim heads total
#define Mrows 8192                 // Sdim*Bdim
#define HEAD_ELEMS (Sdim * HDdim)  // 262144

// ---------------- scratch (device globals; no allocation allowed) ----------
__device__ __nv_bfloat16 g_Ahi[(size_t)Mrows * Ddim];
__device__ __nv_bfloat16 g_Alo[(size_t)Mrows * Ddim];
__device__ __nv_bfloat16 g_Whi[(size_t)Ddim * Ddim];
__device__ __nv_bfloat16 g_Wlo[(size_t)Ddim * Ddim];
__device__ __nv_bfloat16 g_Qhi[(size_t)NB * HEAD_ELEMS];
__device__ __nv_bfloat16 g_Qlo[(size_t)NB * HEAD_ELEMS];
__device__ __nv_bfloat16 g_Khi[(size_t)NB * HEAD_ELEMS];
__device__ __nv_bfloat16 g_Klo[(size_t)NB * HEAD_ELEMS];
__device__ float         g_Vh  [(size_t)NB * HEAD_ELEMS];
__device__ __nv_bfloat16 g_Vthi[(size_t)NB * HEAD_ELEMS];
__device__ __nv_bfloat16 g_Vtlo[(size_t)NB * HEAD_ELEMS];
__device__ float         g_scores [(size_t)NB * HEAD_ELEMS];
__device__ float         g_attn_fb[(size_t)NB * HEAD_ELEMS];
__device__ __nv_bfloat16 g_Phi[(size_t)NB * HEAD_ELEMS];
__device__ __nv_bfloat16 g_Plo[(size_t)NB * HEAD_ELEMS];
__device__ __nv_bfloat16 g_Chi[(size_t)Mrows * Ddim];
__device__ __nv_bfloat16 g_Clo[(size_t)Mrows * Ddim];

// ---------------- PTX helpers (base ISA only) --------------------------------
__device__ __forceinline__ uint32_t smem_u32(const void* p) {
    uint32_t a;
    asm("{ .reg .u64 t; cvta.to.shared.u64 t, %1; cvt.u32.u64 %0, t; }" : "=r"(a) : "l"(p));
    return a;
}
#define CP_ASYNC16(dst, src) \
    asm volatile("cp.async.cg.shared.global [%0], [%1], 16;" :: "r"(dst), "l"(src))
#define CP_COMMIT  asm volatile("cp.async.commit_group;" ::: "memory")
#define CP_WAIT0   asm volatile("cp.async.wait_group 0;" ::: "memory")
#define CP_WAIT1   asm volatile("cp.async.wait_group 1;" ::: "memory")

__device__ __forceinline__ void ldsm4(uint32_t* r, uint32_t addr) {
    asm volatile("ldmatrix.sync.aligned.m8n8.x4.shared.b16 {%0,%1,%2,%3}, [%4];"
                 : "=r"(r[0]), "=r"(r[1]), "=r"(r[2]), "=r"(r[3]) : "r"(addr));
}
__device__ __forceinline__ void mma_bf16(float* c, const uint32_t* a, const uint32_t* b) {
    asm volatile(
        "mma.sync.aligned.m16n8k16.row.col.f32.bf16.bf16.f32 "
        "{%0,%1,%2,%3}, {%4,%5,%6,%7}, {%8,%9}, {%0,%1,%2,%3};"
        : "+f"(c[0]), "+f"(c[1]), "+f"(c[2]), "+f"(c[3])
        : "r"(a[0]), "r"(a[1]), "r"(a[2]), "r"(a[3]), "r"(b[0]), "r"(b[1]));
}

__device__ __forceinline__ void wr_hilo2(__nv_bfloat16* H, __nv_bfloat16* L,
                                         size_t off, float a, float b) {
    __nv_bfloat16 ha = __float2bfloat16(a), hb = __float2bfloat16(b);
    __nv_bfloat162 hv; hv.x = ha; hv.y = hb;
    __nv_bfloat162 lv;
    lv.x = __float2bfloat16(a - __bfloat162float(ha));
    lv.y = __float2bfloat16(b - __bfloat162float(hb));
    *(__nv_bfloat162*)(H + off) = hv;
    *(__nv_bfloat162*)(L + off) = lv;
}

// ---------------- mma.sync NT GEMM -------------------------------------------
// C[M,N] = alpha * A[M,K] * B[N,K]^T with A,B as bf16 hi/lo pairs (3-pass).
// Block 128x256, BK=32, 512 threads; warp tile 32x64 (warps: 4 in m, 4 in n).
// 3-stage cp.async pipeline, one __syncthreads per K-chunk.
#define GBM 128
#define GBN 256
#define GBK 32
#define ROW_B 80                        // smem bytes per tile row (32 bf16 + 8 pad)
#define A_TILE_B (128 * ROW_B)          // 10240
#define B_TILE_B (256 * ROW_B)          // 20480
#define STAGE_B (2 * A_TILE_B + 2 * B_TILE_B)   // 61440
#define NSTAGE 3
#define GEMM_SMEM (NSTAGE * STAGE_B)    // 184320

enum { EP_F32 = 0, EP_BF16 = 1, EP_QK = 2, EP_V = 3 };

// r = s*16 + b (or t*16 + b), c = h*512 + d  ->  ((b*4+h)*512 + s)*512 + d
__device__ __forceinline__ size_t headperm_idx(int r, int c) {
    int s = r >> 4, bb = r & 15, h = c >> 9, d = c & 511;
    return (((size_t)(bb * Hdim + h) * Sdim + s) * HDdim + d);
}

struct GemmArgs {
    const __nv_bfloat16 *Ahi, *Alo, *Bhi, *Blo;
    int lda, ldb, ldc, K;
    size_t bsA, bsB, bsC;
    float* Cf;
    __nv_bfloat16 *Chi, *Clo;
    float alpha;
    int mode;
};

__global__ __launch_bounds__(512, 1)
void mma_gemm(GemmArgs g)
{
    extern __shared__ char smraw[];
    const uint32_t sb = smem_u32(smraw);
    const int tid = threadIdx.x;
    const int lane = tid & 31;
    const int wid = tid >> 5;
    const int wm = wid & 3;       // warp m index (0..3)
    const int wn = wid >> 2;      // warp n index (0..3)
    const int m0 = blockIdx.y * GBM;
    const int n0 = blockIdx.x * GBN;
    const size_t z = blockIdx.z;

    const __nv_bfloat16* Ah = g.Ahi + z * g.bsA;
    const __nv_bfloat16* Al = g.Alo + z * g.bsA;
    const __nv_bfloat16* Bh = g.Bhi + z * g.bsB;
    const __nv_bfloat16* Bl = g.Blo + z * g.bsB;

    float acc[2][8][4];
#pragma unroll
    for (int i = 0; i < 2; i++)
#pragma unroll
        for (int j = 0; j < 8; j++)
#pragma unroll
            for (int x = 0; x < 4; x++) acc[i][j][x] = 0.f;

    // ldmatrix address precompute
    const uint32_t a_mrow = (uint32_t)(wm * 32) + (lane & 15);
    const uint32_t a_kadd = (uint32_t)(((lane >> 4) & 1) << 3);
    const uint32_t b_nrow = (uint32_t)(wn * 64) + (lane & 7) + (((lane >> 4) & 1) << 3);
    const uint32_t b_kadd = (uint32_t)(((lane >> 3) & 1) << 3);

    // cp.async per-thread coordinates (precomputed)
    const int la_row = tid >> 2;          // 0..127 (A tiles: 1 op/thread/tile)
    const int la_cc  = tid & 3;
    const int NCH = g.K >> 5;

    auto issue = [&](int ch, int stg) {
        const int kOff = ch * GBK;
        const uint32_t stb = sb + (uint32_t)stg * STAGE_B;
        // A hi/lo
        {
            uint32_t d = stb + (uint32_t)la_row * ROW_B + (uint32_t)la_cc * 16;
            const size_t so = (size_t)(m0 + la_row) * g.lda + kOff + la_cc * 8;
            CP_ASYNC16(d, Ah + so);
            CP_ASYNC16(d + A_TILE_B, Al + so);
        }
        // B hi/lo (2 ops/thread/tile)
#pragma unroll
        for (int j = 0; j < 2; j++) {
            int id = tid + j * 512;
            int row = id >> 2;
            int cc = id & 3;
            uint32_t d = stb + 2 * A_TILE_B + (uint32_t)row * ROW_B + (uint32_t)cc * 16;
            const size_t so = (size_t)(n0 + row) * g.ldb + kOff + cc * 8;
            CP_ASYNC16(d, Bh + so);
            CP_ASYNC16(d + B_TILE_B, Bl + so);
        }
        CP_COMMIT;
    };

    auto compute = [&](int stg) {
        const uint32_t stb = sb + (uint32_t)stg * STAGE_B;
        const uint32_t ahB = stb;
        const uint32_t alB = stb + A_TILE_B;
        const uint32_t bhB = stb + 2 * A_TILE_B;
        const uint32_t blB = stb + 2 * A_TILE_B + B_TILE_B;
#pragma unroll
        for (int ks = 0; ks < 2; ks++) {
            uint32_t afh[2][4], afl[2][4];
#pragma unroll
            for (int i = 0; i < 2; i++) {
                uint32_t off = (a_mrow + (uint32_t)(i * 16)) * ROW_B +
                               ((uint32_t)(ks * 16) + a_kadd) * 2;
                ldsm4(afh[i], ahB + off);
                ldsm4(afl[i], alB + off);
            }
#pragma unroll
            for (int gnp = 0; gnp < 4; gnp++) {
                uint32_t bfh[4], bfl[4];
                uint32_t off = (b_nrow + (uint32_t)(gnp * 16)) * ROW_B +
                               ((uint32_t)(ks * 16) + b_kadd) * 2;
                ldsm4(bfh, bhB + off);
                ldsm4(bfl, blB + off);
#pragma unroll
                for (int i = 0; i < 2; i++) {
#pragma unroll
                    for (int jj = 0; jj < 2; jj++) {
                        float* c = acc[i][gnp * 2 + jj];
                        mma_bf16(c, afh[i], bfh + jj * 2);
                        mma_bf16(c, afh[i], bfl + jj * 2);
                        mma_bf16(c, afl[i], bfh + jj * 2);
                    }
                }
            }
        }
    };

    // 3-stage pipeline, prefetch depth 2, one sync per chunk
    issue(0, 0);
    issue(1, 1);
    for (int ch = 0; ch < NCH; ch++) {
        CP_WAIT1;               // group(ch) complete (only group(ch+1) may pend)
        __syncthreads();        // all warps done computing chunk ch-1 -> slot reuse safe
        if (ch + 2 < NCH) issue(ch + 2, (ch + 2) % NSTAGE);
        compute(ch % NSTAGE);
    }

    // -------- epilogue --------
    const int quad = lane >> 2, tq = lane & 3;
    const float alpha = g.alpha;
#pragma unroll
    for (int i = 0; i < 2; i++) {
#pragma unroll
        for (int jj = 0; jj < 8; jj++) {
            const int r  = m0 + wm * 32 + i * 16 + quad;
            const int c  = n0 + wn * 64 + jj * 8 + tq * 2;
            const float v0 = acc[i][jj][0] * alpha;
            const float v1 = acc[i][jj][1] * alpha;
            const float v2 = acc[i][jj][2] * alpha;
            const float v3 = acc[i][jj][3] * alpha;
            if (g.mode == EP_F32) {
                float2* p0 = (float2*)(g.Cf + z * g.bsC + (size_t)r * g.ldc + c);
                float2* p1 = (float2*)(g.Cf + z * g.bsC + (size_t)(r + 8) * g.ldc + c);
                float2 a0; a0.x = v0; a0.y = v1; *p0 = a0;
                float2 a1; a1.x = v2; a1.y = v3; *p1 = a1;
            } else if (g.mode == EP_BF16) {
                wr_hilo2(g.Chi, g.Clo, z * g.bsC + (size_t)r * g.ldc + c, v0, v1);
                wr_hilo2(g.Chi, g.Clo, z * g.bsC + (size_t)(r + 8) * g.ldc + c, v2, v3);
            } else if (g.mode == EP_QK) {
                wr_hilo2(g.Chi, g.Clo, headperm_idx(r, c), v0, v1);
                wr_hilo2(g.Chi, g.Clo, headperm_idx(r + 8, c), v2, v3);
            } else { // EP_V : fp32 head-permuted
                size_t o0 = headperm_idx(r, c), o1 = headperm_idx(r + 8, c);
                float2 a0; a0.x = v0; a0.y = v1; *(float2*)(g.Cf + o0) = a0;
                float2 a1; a1.x = v2; a1.y = v3; *(float2*)(g.Cf + o1) = a1;
            }
        }
    }
}

// ---------------- fp32 -> bf16 hi/lo split -----------------------------------
__global__ void cvt_hilo(const float* __restrict__ x, __nv_bfloat16* __restrict__ hi,
                         __nv_bfloat16* __restrict__ lo, int n4)
{
    int i = blockIdx.x * blockDim.x + threadIdx.x;
    if (i >= n4) return;
    float4 v = ((const float4*)x)[i];
    float f[4] = {v.x, v.y, v.z, v.w};
    __nv_bfloat162 h2[2], l2[2];
#pragma unroll
    for (int j = 0; j < 2; j++) {
        __nv_bfloat16 ha = __float2bfloat16(f[j * 2 + 0]);
        __nv_bfloat16 hb = __float2bfloat16(f[j * 2 + 1]);
        h2[j].x = ha; h2[j].y = hb;
        l2[j].x = __float2bfloat16(f[j * 2 + 0] - __bfloat162float(ha));
        l2[j].y = __float2bfloat16(f[j * 2 + 1] - __bfloat162float(hb));
    }
    ((__nv_bfloat162*)hi)[i * 2 + 0] = h2[0];
    ((__nv_bfloat162*)hi)[i * 2 + 1] = h2[1];
    ((__nv_bfloat162*)lo)[i * 2 + 0] = l2[0];
    ((__nv_bfloat162*)lo)[i * 2 + 1] = l2[1];
}

// ---------------- V transpose + split: Vh[gb][t][d] -> Vt[gb][d][t] ---------
__global__ void vtrans_kernel(const float* __restrict__ Vh,
                              __nv_bfloat16* __restrict__ Vthi,
                              __nv_bfloat16* __restrict__ Vtlo)
{
    __shared__ float tile[32][33];
    const int gb = blockIdx.z;
    const int t0 = blockIdx.x * 32;
    const int d0 = blockIdx.y * 32;
    const int tx = threadIdx.x, ty = threadIdx.y;   // 32 x 8
    const float* src = Vh + (size_t)gb * HEAD_ELEMS;
#pragma unroll
    for (int i = 0; i < 32; i += 8)
        tile[ty + i][tx] = src[(size_t)(t0 + ty + i) * HDdim + d0 + tx];
    __syncthreads();
    __nv_bfloat16* dh = Vthi + (size_t)gb * HEAD_ELEMS;
    __nv_bfloat16* dl = Vtlo + (size_t)gb * HEAD_ELEMS;
#pragma unroll
    for (int i = 0; i < 32; i += 8) {
        float v = tile[tx][ty + i];
        __nv_bfloat16 h = __float2bfloat16(v);
        size_t o = (size_t)(d0 + ty + i) * Sdim + t0 + tx;
        dh[o] = h;
        dl[o] = __float2bfloat16(v - __bfloat162float(h));
    }
}

// ---------------- softmax: scores[gb][s][t] -> attn fp32 + P hi/lo ----------
__global__ void softmax_kernel(const float* __restrict__ scores,
                               float* __restrict__ attn,
                               __nv_bfloat16* __restrict__ Phi,
                               __nv_bfloat16* __restrict__ Plo)
{
    int gwarp = (blockIdx.x * blockDim.x + threadIdx.x) >> 5;
    int lane  = threadIdx.x & 31;
    if (gwarp >= NB * Sdim) return;
    int gb = gwarp >> 9;         // head slot (b*4+h)
    int s  = gwarp & 511;
    int b  = gb >> 2;
    int h  = gb & 3;

    const float* row = scores + ((size_t)gb * Sdim + s) * Sdim;
    float vals[16];
    float mx = -1e30f;
#pragma unroll
    for (int i = 0; i < 16; i++) {
        vals[i] = row[lane + i * 32];
        mx = fmaxf(mx, vals[i]);
    }
#pragma unroll
    for (int o = 16; o > 0; o >>= 1) mx = fmaxf(mx, __shfl_xor_sync(0xffffffffu, mx, o));
    float sum = 0.f;
#pragma unroll
    for (int i = 0; i < 16; i++) {
        vals[i] = expf(vals[i] - mx);
        sum += vals[i];
    }
#pragma unroll
    for (int o = 16; o > 0; o >>= 1) sum += __shfl_xor_sync(0xffffffffu, sum, o);
    float inv = 1.f / sum;

    float* arow = attn + (((size_t)b * Sdim + s) * Hdim + h) * HDdim;   // [b][s][h][t]
    __nv_bfloat16* ph = Phi + ((size_t)gb * Sdim + s) * Sdim;
    __nv_bfloat16* pl = Plo + ((size_t)gb * Sdim + s) * Sdim;
#pragma unroll
    for (int i = 0; i < 16; i++) {
        float p = vals[i] * inv;
        arow[lane + i * 32] = p;
        __nv_bfloat16 hh = __float2bfloat16(p);
        ph[lane + i * 32] = hh;
        pl[lane + i * 32] = __float2bfloat16(p - __bfloat162float(hh));
    }
}

// ---------------- launch -----------------------------------------------------
extern "C" void kernel_launch(void* const* d_in, const int* in_sizes, int n_in,
                              void* d_out, int out_size)
{
    const float* q  = (const float*)d_in[0];
    const float* k  = (const float*)d_in[1];
    const float* v  = (const float*)d_in[2];
    const float* Wq = (const float*)d_in[3];
    const float* Wk = (const float*)d_in[4];
    const float* Wv = (const float*)d_in[5];
    const float* Wo = (const float*)d_in[6];
    float* out = (float*)d_out;

    __nv_bfloat16 *Ahi, *Alo, *Whi, *Wlo, *Qhi, *Qlo, *Khi, *Klo, *Vthi, *Vtlo, *Phi, *Plo, *Chi, *Clo;
    float *Vh, *Sc, *At;
    cudaGetSymbolAddress((void**)&Ahi, g_Ahi);   cudaGetSymbolAddress((void**)&Alo, g_Alo);
    cudaGetSymbolAddress((void**)&Whi, g_Whi);   cudaGetSymbolAddress((void**)&Wlo, g_Wlo);
    cudaGetSymbolAddress((void**)&Qhi, g_Qhi);   cudaGetSymbolAddress((void**)&Qlo, g_Qlo);
    cudaGetSymbolAddress((void**)&Khi, g_Khi);   cudaGetSymbolAddress((void**)&Klo, g_Klo);
    cudaGetSymbolAddress((void**)&Vh,  g_Vh);
    cudaGetSymbolAddress((void**)&Vthi, g_Vthi); cudaGetSymbolAddress((void**)&Vtlo, g_Vtlo);
    cudaGetSymbolAddress((void**)&Sc,  g_scores);
    cudaGetSymbolAddress((void**)&At,  g_attn_fb);
    cudaGetSymbolAddress((void**)&Phi, g_Phi);   cudaGetSymbolAddress((void**)&Plo, g_Plo);
    cudaGetSymbolAddress((void**)&Chi, g_Chi);   cudaGetSymbolAddress((void**)&Clo, g_Clo);

    const long MAIN_OUT = (long)Mrows * Ddim;
    float* attn_out = ((long)out_size >= 2 * MAIN_OUT) ? (out + MAIN_OUT) : At;

    cudaFuncSetAttribute(mma_gemm, cudaFuncAttributeMaxDynamicSharedMemorySize, GEMM_SMEM);

    const int nAct4 = (Mrows * Ddim) / 4;
    const int nW4   = (Ddim * Ddim) / 4;
    dim3 cblk(256);
    dim3 gActCvt(nAct4 / 256), gWCvt(nW4 / 256);
    dim3 blk(512);
    dim3 gProj(Ddim / GBN, Mrows / GBM, 1);      // 8 x 64 = 512 CTAs
    dim3 gAttn(Sdim / GBN, Sdim / GBM, NB);      // 2 x 4 x 64 = 512 CTAs

    GemmArgs ga;
    ga.lda = Ddim; ga.ldb = Ddim; ga.ldc = Ddim; ga.K = Ddim;
    ga.bsA = 0; ga.bsB = 0; ga.bsC = 0;
    ga.alpha = 1.0f;

    // ---- Q projection ----
    cvt_hilo<<<gActCvt, cblk>>>(q, Ahi, Alo, nAct4);
    cvt_hilo<<<gWCvt, cblk>>>(Wq, Whi, Wlo, nW4);
    ga.Ahi = Ahi; ga.Alo = Alo; ga.Bhi = Whi; ga.Blo = Wlo;
    ga.Cf = nullptr; ga.Chi = Qhi; ga.Clo = Qlo; ga.mode = EP_QK;
    mma_gemm<<<gProj, blk, GEMM_SMEM>>>(ga);
    // ---- K projection ----
    cvt_hilo<<<gActCvt, cblk>>>(k, Ahi, Alo, nAct4);
    cvt_hilo<<<gWCvt, cblk>>>(Wk, Whi, Wlo, nW4);
    ga.Chi = Khi; ga.Clo = Klo; ga.mode = EP_QK;
    mma_gemm<<<gProj, blk, GEMM_SMEM>>>(ga);
    // ---- V projection (fp32 head-permuted) ----
    cvt_hilo<<<gActCvt, cblk>>>(v, Ahi, Alo, nAct4);
    cvt_hilo<<<gWCvt, cblk>>>(Wv, Whi, Wlo, nW4);
    ga.Cf = Vh; ga.Chi = nullptr; ga.Clo = nullptr; ga.mode = EP_V;
    mma_gemm<<<gProj, blk, GEMM_SMEM>>>(ga);
    // ---- V transpose + bf16 split ----
    {
        dim3 tb(32, 8);
        dim3 tg(Sdim / 32, HDdim / 32, NB);
        vtrans_kernel<<<tg, tb>>>(Vh, Vthi, Vtlo);
    }
    // ---- scores = Q K^T / sqrt(hd) ----
    {
        GemmArgs gs;
        gs.Ahi = Qhi; gs.Alo = Qlo; gs.Bhi = Khi; gs.Blo = Klo;
        gs.lda = HDdim; gs.ldb = HDdim; gs.ldc = Sdim; gs.K = HDdim;
        gs.bsA = HEAD_ELEMS; gs.bsB = HEAD_ELEMS; gs.bsC = HEAD_ELEMS;
        gs.Cf = Sc; gs.Chi = nullptr; gs.Clo = nullptr;
        gs.alpha = 0.044194173824159223f;   // 1/sqrt(512)
        gs.mode = EP_F32;
        mma_gemm<<<gAttn, blk, GEMM_SMEM>>>(gs);
    }
    // ---- softmax -> attn fp32 output + P hi/lo ----
    {
        int totalWarps = NB * Sdim;
        int blocks = (totalWarps * 32) / 256;
        softmax_kernel<<<blocks, 256>>>(Sc, attn_out, Phi, Plo);
    }
    // ---- context = P V  -> Chi/Clo in (b,h,s,d) linear order ----
    {
        GemmArgs gp;
        gp.Ahi = Phi; gp.Alo = Plo; gp.Bhi = Vthi; gp.Blo = Vtlo;
        gp.lda = Sdim; gp.ldb = Sdim; gp.ldc = HDdim; gp.K = Sdim;
        gp.bsA = HEAD_ELEMS; gp.bsB = HEAD_ELEMS; gp.bsC = HEAD_ELEMS;
        gp.Cf = nullptr; gp.Chi = Chi; gp.Clo = Clo;
        gp.alpha = 1.0f; gp.mode = EP_BF16;
        mma_gemm<<<gAttn, blk, GEMM_SMEM>>>(gp);
    }
    // ---- output = C @ Wo^T ----
    cvt_hilo<<<gWCvt, cblk>>>(Wo, Whi, Wlo, nW4);
    {
        GemmArgs go;
        go.Ahi = Chi; go.Alo = Clo; go.Bhi = Whi; go.Blo = Wlo;
        go.lda = Ddim; go.ldb = Ddim; go.ldc = Ddim; go.K = Ddim;
        go.bsA = 0; go.bsB = 0; go.bsC = 0;
        go.Cf = out; go.Chi = nullptr; go.Clo = nullptr;
        go.alpha = 1.0f; go.mode = EP_F32;
        mma_gemm<<<gProj, blk, GEMM_SMEM>>>(go);
    }
}

// round 5
// speedup vs baseline: 2.2078x; 1.0290x over previous
#include <cuda_runtime.h>
#include <cuda_bf16.h>
#include <stdint.h>
#include <math.h>

// Problem constants
#define Sdim 512
#define Bdim 16
#define Ddim 2048
#define Hdim 4
#define HDdim 512
#define NB 64                      // Hdim*Bdim heads total
#define Mrows 8192                 // Sdim*Bdim
#define HEAD_ELEMS (Sdim * HDdim)  // 262144
#define ACT_ELEMS ((size_t)Mrows * Ddim)
#define W_ELEMS ((size_t)Ddim * Ddim)

// ---------------- scratch (device globals; no allocation allowed) ----------
__device__ __nv_bfloat16 g_Acthi[3 * ACT_ELEMS];
__device__ __nv_bfloat16 g_Actlo[3 * ACT_ELEMS];
__device__ __nv_bfloat16 g_Whi[4 * W_ELEMS];
__device__ __nv_bfloat16 g_Wlo[4 * W_ELEMS];
__device__ __nv_bfloat16 g_Qhi[(size_t)NB * HEAD_ELEMS];
__device__ __nv_bfloat16 g_Qlo[(size_t)NB * HEAD_ELEMS];
__device__ __nv_bfloat16 g_Khi[(size_t)NB * HEAD_ELEMS];
__device__ __nv_bfloat16 g_Klo[(size_t)NB * HEAD_ELEMS];
__device__ float         g_Vh  [(size_t)NB * HEAD_ELEMS];
__device__ __nv_bfloat16 g_Vthi[(size_t)NB * HEAD_ELEMS];
__device__ __nv_bfloat16 g_Vtlo[(size_t)NB * HEAD_ELEMS];
__device__ float         g_scores [(size_t)NB * HEAD_ELEMS];
__device__ float         g_attn_fb[(size_t)NB * HEAD_ELEMS];
__device__ __nv_bfloat16 g_Phi[(size_t)NB * HEAD_ELEMS];
__device__ __nv_bfloat16 g_Plo[(size_t)NB * HEAD_ELEMS];
__device__ __nv_bfloat16 g_Chi[ACT_ELEMS];
__device__ __nv_bfloat16 g_Clo[ACT_ELEMS];

// ---------------- PTX helpers (base ISA only) --------------------------------
__device__ __forceinline__ uint32_t smem_u32(const void* p) {
    uint32_t a;
    asm("{ .reg .u64 t; cvta.to.shared.u64 t, %1; cvt.u32.u64 %0, t; }" : "=r"(a) : "l"(p));
    return a;
}
#define CP_ASYNC16(dst, src) \
    asm volatile("cp.async.cg.shared.global [%0], [%1], 16;" :: "r"(dst), "l"(src))
#define CP_COMMIT  asm volatile("cp.async.commit_group;" ::: "memory")
#define CP_WAIT0   asm volatile("cp.async.wait_group 0;" ::: "memory")
#define CP_WAIT1   asm volatile("cp.async.wait_group 1;" ::: "memory")

__device__ __forceinline__ void ldsm4(uint32_t* r, uint32_t addr) {
    asm volatile("ldmatrix.sync.aligned.m8n8.x4.shared.b16 {%0,%1,%2,%3}, [%4];"
                 : "=r"(r[0]), "=r"(r[1]), "=r"(r[2]), "=r"(r[3]) : "r"(addr));
}
__device__ __forceinline__ void mma_bf16(float* c, const uint32_t* a, const uint32_t* b) {
    asm volatile(
        "mma.sync.aligned.m16n8k16.row.col.f32.bf16.bf16.f32 "
        "{%0,%1,%2,%3}, {%4,%5,%6,%7}, {%8,%9}, {%0,%1,%2,%3};"
        : "+f"(c[0]), "+f"(c[1]), "+f"(c[2]), "+f"(c[3])
        : "r"(a[0]), "r"(a[1]), "r"(a[2]), "r"(a[3]), "r"(b[0]), "r"(b[1]));
}

__device__ __forceinline__ void wr_hilo2(__nv_bfloat16* H, __nv_bfloat16* L,
                                         size_t off, float a, float b) {
    __nv_bfloat16 ha = __float2bfloat16(a), hb = __float2bfloat16(b);
    __nv_bfloat162 hv; hv.x = ha; hv.y = hb;
    __nv_bfloat162 lv;
    lv.x = __float2bfloat16(a - __bfloat162float(ha));
    lv.y = __float2bfloat16(b - __bfloat162float(hb));
    *(__nv_bfloat162*)(H + off) = hv;
    *(__nv_bfloat162*)(L + off) = lv;
}

// ---------------- mma.sync NT GEMM -------------------------------------------
// C[M,N] = alpha * A[M,K] * B[N,K]^T with A,B as bf16 hi/lo pairs (3-pass).
// Block 128x256, BK=32, 512 threads; warp tile 32x64 (warps: 4 in m, 4 in n).
// 3-stage cp.async pipeline, one __syncthreads per K-chunk.
#define GBM 128
#define GBN 256
#define GBK 32
#define ROW_B 80                        // smem bytes per tile row (32 bf16 + 8 pad)
#define A_TILE_B (128 * ROW_B)          // 10240
#define B_TILE_B (256 * ROW_B)          // 20480
#define STAGE_B (2 * A_TILE_B + 2 * B_TILE_B)   // 61440
#define NSTAGE 3
#define GEMM_SMEM (NSTAGE * STAGE_B)    // 184320

enum { EP_F32 = 0, EP_BF16 = 1, EP_QK = 2, EP_V = 3, EP_QKV3 = 4 };

// r = s*16 + b (or t*16 + b), c = h*512 + d  ->  ((b*4+h)*512 + s)*512 + d
__device__ __forceinline__ size_t headperm_idx(int r, int c) {
    int s = r >> 4, bb = r & 15, h = c >> 9, d = c & 511;
    return (((size_t)(bb * Hdim + h) * Sdim + s) * HDdim + d);
}

struct GemmArgs {
    const __nv_bfloat16 *Ahi, *Alo, *Bhi, *Blo;
    int lda, ldb, ldc, K;
    size_t bsA, bsB, bsC;
    float* Cf;
    __nv_bfloat16 *Chi, *Clo;    // dst pair (z==0 for QKV3)
    __nv_bfloat16 *Chi2, *Clo2;  // dst pair for z==1 (QKV3)
    float alpha;
    int mode;
};

__global__ __launch_bounds__(512, 1)
void mma_gemm(GemmArgs g)
{
    extern __shared__ char smraw[];
    const uint32_t sb = smem_u32(smraw);
    const int tid = threadIdx.x;
    const int lane = tid & 31;
    const int wid = tid >> 5;
    const int wm = wid & 3;       // warp m index (0..3)
    const int wn = wid >> 2;      // warp n index (0..3)
    const int m0 = blockIdx.y * GBM;
    const int n0 = blockIdx.x * GBN;
    const size_t z = blockIdx.z;

    const __nv_bfloat16* Ah = g.Ahi + z * g.bsA;
    const __nv_bfloat16* Al = g.Alo + z * g.bsA;
    const __nv_bfloat16* Bh = g.Bhi + z * g.bsB;
    const __nv_bfloat16* Bl = g.Blo + z * g.bsB;

    float acc[2][8][4];
#pragma unroll
    for (int i = 0; i < 2; i++)
#pragma unroll
        for (int j = 0; j < 8; j++)
#pragma unroll
            for (int x = 0; x < 4; x++) acc[i][j][x] = 0.f;

    // ldmatrix address precompute
    const uint32_t a_mrow = (uint32_t)(wm * 32) + (lane & 15);
    const uint32_t a_kadd = (uint32_t)(((lane >> 4) & 1) << 3);
    const uint32_t b_nrow = (uint32_t)(wn * 64) + (lane & 7) + (((lane >> 4) & 1) << 3);
    const uint32_t b_kadd = (uint32_t)(((lane >> 3) & 1) << 3);

    // cp.async per-thread coordinates
    const int la_row = tid >> 2;
    const int la_cc  = tid & 3;
    const int NCH = g.K >> 5;

    auto issue = [&](int ch, int stg) {
        const int kOff = ch * GBK;
        const uint32_t stb = sb + (uint32_t)stg * STAGE_B;
        {
            uint32_t d = stb + (uint32_t)la_row * ROW_B + (uint32_t)la_cc * 16;
            const size_t so = (size_t)(m0 + la_row) * g.lda + kOff + la_cc * 8;
            CP_ASYNC16(d, Ah + so);
            CP_ASYNC16(d + A_TILE_B, Al + so);
        }
#pragma unroll
        for (int j = 0; j < 2; j++) {
            int id = tid + j * 512;
            int row = id >> 2;
            int cc = id & 3;
            uint32_t d = stb + 2 * A_TILE_B + (uint32_t)row * ROW_B + (uint32_t)cc * 16;
            const size_t so = (size_t)(n0 + row) * g.ldb + kOff + cc * 8;
            CP_ASYNC16(d, Bh + so);
            CP_ASYNC16(d + B_TILE_B, Bl + so);
        }
        CP_COMMIT;
    };

    auto compute = [&](int stg) {
        const uint32_t stb = sb + (uint32_t)stg * STAGE_B;
        const uint32_t ahB = stb;
        const uint32_t alB = stb + A_TILE_B;
        const uint32_t bhB = stb + 2 * A_TILE_B;
        const uint32_t blB = stb + 2 * A_TILE_B + B_TILE_B;
#pragma unroll
        for (int ks = 0; ks < 2; ks++) {
            uint32_t afh[2][4], afl[2][4];
#pragma unroll
            for (int i = 0; i < 2; i++) {
                uint32_t off = (a_mrow + (uint32_t)(i * 16)) * ROW_B +
                               ((uint32_t)(ks * 16) + a_kadd) * 2;
                ldsm4(afh[i], ahB + off);
                ldsm4(afl[i], alB + off);
            }
#pragma unroll
            for (int gnp = 0; gnp < 4; gnp++) {
                uint32_t bfh[4], bfl[4];
                uint32_t off = (b_nrow + (uint32_t)(gnp * 16)) * ROW_B +
                               ((uint32_t)(ks * 16) + b_kadd) * 2;
                ldsm4(bfh, bhB + off);
                ldsm4(bfl, blB + off);
                // pass-outermost: consecutive MMAs hit independent accumulators
#pragma unroll
                for (int i = 0; i < 2; i++)
#pragma unroll
                    for (int jj = 0; jj < 2; jj++)
                        mma_bf16(acc[i][gnp * 2 + jj], afh[i], bfh + jj * 2);
#pragma unroll
                for (int i = 0; i < 2; i++)
#pragma unroll
                    for (int jj = 0; jj < 2; jj++)
                        mma_bf16(acc[i][gnp * 2 + jj], afh[i], bfl + jj * 2);
#pragma unroll
                for (int i = 0; i < 2; i++)
#pragma unroll
                    for (int jj = 0; jj < 2; jj++)
                        mma_bf16(acc[i][gnp * 2 + jj], afl[i], bfh + jj * 2);
            }
        }
    };

    issue(0, 0);
    issue(1, 1);
    for (int ch = 0; ch < NCH; ch++) {
        CP_WAIT1;
        __syncthreads();
        if (ch + 2 < NCH) issue(ch + 2, (ch + 2) % NSTAGE);
        compute(ch % NSTAGE);
    }

    // -------- epilogue --------
    const int quad = lane >> 2, tq = lane & 3;
    const float alpha = g.alpha;
#pragma unroll
    for (int i = 0; i < 2; i++) {
#pragma unroll
        for (int jj = 0; jj < 8; jj++) {
            const int r  = m0 + wm * 32 + i * 16 + quad;
            const int c  = n0 + wn * 64 + jj * 8 + tq * 2;
            const float v0 = acc[i][jj][0] * alpha;
            const float v1 = acc[i][jj][1] * alpha;
            const float v2 = acc[i][jj][2] * alpha;
            const float v3 = acc[i][jj][3] * alpha;
            if (g.mode == EP_F32) {
                float2* p0 = (float2*)(g.Cf + z * g.bsC + (size_t)r * g.ldc + c);
                float2* p1 = (float2*)(g.Cf + z * g.bsC + (size_t)(r + 8) * g.ldc + c);
                float2 a0; a0.x = v0; a0.y = v1; *p0 = a0;
                float2 a1; a1.x = v2; a1.y = v3; *p1 = a1;
            } else if (g.mode == EP_BF16) {
                wr_hilo2(g.Chi, g.Clo, z * g.bsC + (size_t)r * g.ldc + c, v0, v1);
                wr_hilo2(g.Chi, g.Clo, z * g.bsC + (size_t)(r + 8) * g.ldc + c, v2, v3);
            } else if (g.mode == EP_QKV3) {
                size_t o0 = headperm_idx(r, c), o1 = headperm_idx(r + 8, c);
                if (z == 0) {
                    wr_hilo2(g.Chi, g.Clo, o0, v0, v1);
                    wr_hilo2(g.Chi, g.Clo, o1, v2, v3);
                } else if (z == 1) {
                    wr_hilo2(g.Chi2, g.Clo2, o0, v0, v1);
                    wr_hilo2(g.Chi2, g.Clo2, o1, v2, v3);
                } else {
                    float2 a0; a0.x = v0; a0.y = v1; *(float2*)(g.Cf + o0) = a0;
                    float2 a1; a1.x = v2; a1.y = v3; *(float2*)(g.Cf + o1) = a1;
                }
            }
        }
    }
}

// ---------------- fp32 -> bf16 hi/lo split (single tensor) -------------------
__global__ void cvt_hilo(const float* __restrict__ x, __nv_bfloat16* __restrict__ hi,
                         __nv_bfloat16* __restrict__ lo, int n4)
{
    int i = blockIdx.x * blockDim.x + threadIdx.x;
    if (i >= n4) return;
    float4 v = ((const float4*)x)[i];
    float f[4] = {v.x, v.y, v.z, v.w};
    __nv_bfloat162 h2[2], l2[2];
#pragma unroll
    for (int j = 0; j < 2; j++) {
        __nv_bfloat16 ha = __float2bfloat16(f[j * 2 + 0]);
        __nv_bfloat16 hb = __float2bfloat16(f[j * 2 + 1]);
        h2[j].x = ha; h2[j].y = hb;
        l2[j].x = __float2bfloat16(f[j * 2 + 0] - __bfloat162float(ha));
        l2[j].y = __float2bfloat16(f[j * 2 + 1] - __bfloat162float(hb));
    }
    ((__nv_bfloat162*)hi)[i * 2 + 0] = h2[0];
    ((__nv_bfloat162*)hi)[i * 2 + 1] = h2[1];
    ((__nv_bfloat162*)lo)[i * 2 + 0] = l2[0];
    ((__nv_bfloat162*)lo)[i * 2 + 1] = l2[1];
}

// ---------------- fp32 -> bf16 hi/lo split (q,k,v combined, z picks) --------
__global__ void cvt_acts(const float* __restrict__ q, const float* __restrict__ k,
                         const float* __restrict__ v,
                         __nv_bfloat16* __restrict__ hi, __nv_bfloat16* __restrict__ lo,
                         int n4)
{
    int i = blockIdx.x * blockDim.x + threadIdx.x;
    if (i >= n4) return;
    const int zz = blockIdx.z;
    const float* x = (zz == 0) ? q : (zz == 1) ? k : v;
    const size_t base2 = (size_t)zz * (ACT_ELEMS / 2);   // in bf162 units
    float4 vv = ((const float4*)x)[i];
    float f[4] = {vv.x, vv.y, vv.z, vv.w};
    __nv_bfloat162 h2[2], l2[2];
#pragma unroll
    for (int j = 0; j < 2; j++) {
        __nv_bfloat16 ha = __float2bfloat16(f[j * 2 + 0]);
        __nv_bfloat16 hb = __float2bfloat16(f[j * 2 + 1]);
        h2[j].x = ha; h2[j].y = hb;
        l2[j].x = __float2bfloat16(f[j * 2 + 0] - __bfloat162float(ha));
        l2[j].y = __float2bfloat16(f[j * 2 + 1] - __bfloat162float(hb));
    }
    ((__nv_bfloat162*)hi)[base2 + i * 2 + 0] = h2[0];
    ((__nv_bfloat162*)hi)[base2 + i * 2 + 1] = h2[1];
    ((__nv_bfloat162*)lo)[base2 + i * 2 + 0] = l2[0];
    ((__nv_bfloat162*)lo)[base2 + i * 2 + 1] = l2[1];
}

// ---------------- V transpose + split: Vh[gb][t][d] -> Vt[gb][d][t] ---------
__global__ void vtrans_kernel(const float* __restrict__ Vh,
                              __nv_bfloat16* __restrict__ Vthi,
                              __nv_bfloat16* __restrict__ Vtlo)
{
    __shared__ float tile[32][33];
    const int gb = blockIdx.z;
    const int t0 = blockIdx.x * 32;
    const int d0 = blockIdx.y * 32;
    const int tx = threadIdx.x, ty = threadIdx.y;   // 32 x 8
    const float* src = Vh + (size_t)gb * HEAD_ELEMS;
#pragma unroll
    for (int i = 0; i < 32; i += 8)
        tile[ty + i][tx] = src[(size_t)(t0 + ty + i) * HDdim + d0 + tx];
    __syncthreads();
    __nv_bfloat16* dh = Vthi + (size_t)gb * HEAD_ELEMS;
    __nv_bfloat16* dl = Vtlo + (size_t)gb * HEAD_ELEMS;
#pragma unroll
    for (int i = 0; i < 32; i += 8) {
        float v = tile[tx][ty + i];
        __nv_bfloat16 h = __float2bfloat16(v);
        size_t o = (size_t)(d0 + ty + i) * Sdim + t0 + tx;
        dh[o] = h;
        dl[o] = __float2bfloat16(v - __bfloat162float(h));
    }
}

// ---------------- softmax: scores[gb][s][t] -> attn fp32 + P hi/lo ----------
__global__ void softmax_kernel(const float* __restrict__ scores,
                               float* __restrict__ attn,
                               __nv_bfloat16* __restrict__ Phi,
                               __nv_bfloat16* __restrict__ Plo)
{
    int gwarp = (blockIdx.x * blockDim.x + threadIdx.x) >> 5;
    int lane  = threadIdx.x & 31;
    if (gwarp >= NB * Sdim) return;
    int gb = gwarp >> 9;
    int s  = gwarp & 511;
    int b  = gb >> 2;
    int h  = gb & 3;

    const float* row = scores + ((size_t)gb * Sdim + s) * Sdim;
    float vals[16];
    float mx = -1e30f;
#pragma unroll
    for (int i = 0; i < 16; i++) {
        vals[i] = row[lane + i * 32];
        mx = fmaxf(mx, vals[i]);
    }
#pragma unroll
    for (int o = 16; o > 0; o >>= 1) mx = fmaxf(mx, __shfl_xor_sync(0xffffffffu, mx, o));
    float sum = 0.f;
#pragma unroll
    for (int i = 0; i < 16; i++) {
        vals[i] = expf(vals[i] - mx);
        sum += vals[i];
    }
#pragma unroll
    for (int o = 16; o > 0; o >>= 1) sum += __shfl_xor_sync(0xffffffffu, sum, o);
    float inv = 1.f / sum;

    float* arow = attn + (((size_t)b * Sdim + s) * Hdim + h) * HDdim;
    __nv_bfloat16* ph = Phi + ((size_t)gb * Sdim + s) * Sdim;
    __nv_bfloat16* pl = Plo + ((size_t)gb * Sdim + s) * Sdim;
#pragma unroll
    for (int i = 0; i < 16; i++) {
        float p = vals[i] * inv;
        arow[lane + i * 32] = p;
        __nv_bfloat16 hh = __float2bfloat16(p);
        ph[lane + i * 32] = hh;
        pl[lane + i * 32] = __float2bfloat16(p - __bfloat162float(hh));
    }
}

// ---------------- launch -----------------------------------------------------
extern "C" void kernel_launch(void* const* d_in, const int* in_sizes, int n_in,
                              void* d_out, int out_size)
{
    const float* q  = (const float*)d_in[0];
    const float* k  = (const float*)d_in[1];
    const float* v  = (const float*)d_in[2];
    const float* Wq = (const float*)d_in[3];
    const float* Wk = (const float*)d_in[4];
    const float* Wv = (const float*)d_in[5];
    const float* Wo = (const float*)d_in[6];
    float* out = (float*)d_out;

    __nv_bfloat16 *Acthi, *Actlo, *Whi, *Wlo, *Qhi, *Qlo, *Khi, *Klo, *Vthi, *Vtlo, *Phi, *Plo, *Chi, *Clo;
    float *Vh, *Sc, *At;
    cudaGetSymbolAddress((void**)&Acthi, g_Acthi); cudaGetSymbolAddress((void**)&Actlo, g_Actlo);
    cudaGetSymbolAddress((void**)&Whi, g_Whi);   cudaGetSymbolAddress((void**)&Wlo, g_Wlo);
    cudaGetSymbolAddress((void**)&Qhi, g_Qhi);   cudaGetSymbolAddress((void**)&Qlo, g_Qlo);
    cudaGetSymbolAddress((void**)&Khi, g_Khi);   cudaGetSymbolAddress((void**)&Klo, g_Klo);
    cudaGetSymbolAddress((void**)&Vh,  g_Vh);
    cudaGetSymbolAddress((void**)&Vthi, g_Vthi); cudaGetSymbolAddress((void**)&Vtlo, g_Vtlo);
    cudaGetSymbolAddress((void**)&Sc,  g_scores);
    cudaGetSymbolAddress((void**)&At,  g_attn_fb);
    cudaGetSymbolAddress((void**)&Phi, g_Phi);   cudaGetSymbolAddress((void**)&Plo, g_Plo);
    cudaGetSymbolAddress((void**)&Chi, g_Chi);   cudaGetSymbolAddress((void**)&Clo, g_Clo);

    const long MAIN_OUT = (long)Mrows * Ddim;
    float* attn_out = ((long)out_size >= 2 * MAIN_OUT) ? (out + MAIN_OUT) : At;

    cudaFuncSetAttribute(mma_gemm, cudaFuncAttributeMaxDynamicSharedMemorySize, GEMM_SMEM);

    const int nAct4 = (int)(ACT_ELEMS / 4);
    const int nW4   = (int)(W_ELEMS / 4);
    dim3 cblk(256);
    dim3 gWCvt(nW4 / 256);
    dim3 gActCvt(nAct4 / 256, 1, 3);
    dim3 blk(512);
    dim3 gQKV(Ddim / GBN, Mrows / GBM, 3);       // 8 x 64 x 3 = 1536 CTAs
    dim3 gProj(Ddim / GBN, Mrows / GBM, 1);
    dim3 gAttn(Sdim / GBN, Sdim / GBM, NB);      // 2 x 4 x 64

    // 0-3: weight conversions (Wq,Wk,Wv,Wo)
    cvt_hilo<<<gWCvt, cblk>>>(Wq, Whi + 0 * W_ELEMS, Wlo + 0 * W_ELEMS, nW4);
    cvt_hilo<<<gWCvt, cblk>>>(Wk, Whi + 1 * W_ELEMS, Wlo + 1 * W_ELEMS, nW4);
    cvt_hilo<<<gWCvt, cblk>>>(Wv, Whi + 2 * W_ELEMS, Wlo + 2 * W_ELEMS, nW4);
    cvt_hilo<<<gWCvt, cblk>>>(Wo, Whi + 3 * W_ELEMS, Wlo + 3 * W_ELEMS, nW4);
    // 4: all three activation conversions
    cvt_acts<<<gActCvt, cblk>>>(q, k, v, Acthi, Actlo, nAct4);
    // 5: fused Q/K/V projection (profiled by ncu -s 5)
    {
        GemmArgs ga;
        ga.Ahi = Acthi; ga.Alo = Actlo; ga.Bhi = Whi; ga.Blo = Wlo;
        ga.lda = Ddim; ga.ldb = Ddim; ga.ldc = Ddim; ga.K = Ddim;
        ga.bsA = ACT_ELEMS; ga.bsB = W_ELEMS; ga.bsC = 0;
        ga.Cf = Vh;                       // z==2 dst
        ga.Chi = Qhi; ga.Clo = Qlo;       // z==0 dst
        ga.Chi2 = Khi; ga.Clo2 = Klo;     // z==1 dst
        ga.alpha = 1.0f; ga.mode = EP_QKV3;
        mma_gemm<<<gQKV, blk, GEMM_SMEM>>>(ga);
    }
    // 6: V transpose + bf16 split
    {
        dim3 tb(32, 8);
        dim3 tg(Sdim / 32, HDdim / 32, NB);
        vtrans_kernel<<<tg, tb>>>(Vh, Vthi, Vtlo);
    }
    // 7: scores = Q K^T / sqrt(hd)
    {
        GemmArgs gs;
        gs.Ahi = Qhi; gs.Alo = Qlo; gs.Bhi = Khi; gs.Blo = Klo;
        gs.lda = HDdim; gs.ldb = HDdim; gs.ldc = Sdim; gs.K = HDdim;
        gs.bsA = HEAD_ELEMS; gs.bsB = HEAD_ELEMS; gs.bsC = HEAD_ELEMS;
        gs.Cf = Sc; gs.Chi = nullptr; gs.Clo = nullptr; gs.Chi2 = nullptr; gs.Clo2 = nullptr;
        gs.alpha = 0.044194173824159223f;
        gs.mode = EP_F32;
        mma_gemm<<<gAttn, blk, GEMM_SMEM>>>(gs);
    }
    // 8: softmax
    {
        int totalWarps = NB * Sdim;
        int blocks = (totalWarps * 32) / 256;
        softmax_kernel<<<blocks, 256>>>(Sc, attn_out, Phi, Plo);
    }
    // 9: context = P V -> Chi/Clo in (b,h,s,d) linear order
    {
        GemmArgs gp;
        gp.Ahi = Phi; gp.Alo = Plo; gp.Bhi = Vthi; gp.Blo = Vtlo;
        gp.lda = Sdim; gp.ldb = Sdim; gp.ldc = HDdim; gp.K = Sdim;
        gp.bsA = HEAD_ELEMS; gp.bsB = HEAD_ELEMS; gp.bsC = HEAD_ELEMS;
        gp.Cf = nullptr; gp.Chi = Chi; gp.Clo = Clo; gp.Chi2 = nullptr; gp.Clo2 = nullptr;
        gp.alpha = 1.0f; gp.mode = EP_BF16;
        mma_gemm<<<gAttn, blk, GEMM_SMEM>>>(gp);
    }
    // 10: output = C @ Wo^T
    {
        GemmArgs go;
        go.Ahi = Chi; go.Alo = Clo; go.Bhi = Whi + 3 * W_ELEMS; go.Blo = Wlo + 3 * W_ELEMS;
        go.lda = Ddim; go.ldb = Ddim; go.ldc = Ddim; go.K = Ddim;
        go.bsA = 0; go.bsB = 0; go.bsC = 0;
        go.Cf = out; go.Chi = nullptr; go.Clo = nullptr; go.Chi2 = nullptr; go.Clo2 = nullptr;
        go.alpha = 1.0f; go.mode = EP_F32;
        mma_gemm<<<gProj, blk, GEMM_SMEM>>>(go);
    }
}